// round 1
// baseline (speedup 1.0000x reference)
#include <cuda_runtime.h>
#include <math_constants.h>

// Problem constants
#define BB 2
#define SS 2048
#define DD 1024
#define HH 16
#define DK 64

// Scratch (allocation-free: __device__ globals)
__device__ float g_q[(size_t)BB * SS * DD];
__device__ float g_k[(size_t)BB * SS * DD];
__device__ float g_v[(size_t)BB * SS * DD];
__device__ float g_ctx[(size_t)BB * SS * DD];
__device__ float g_po[(size_t)BB * SS * DD];
__device__ float g_attn[(size_t)BB * HH * SS * SS];

// ---------------------------------------------------------------------------
// Tiled GEMM: C = alpha * A @ op(B)
//   TRANS_B = true : C[m,n] = sum_k A[m,k] * B[n,k]   (A row-major MxK, B row-major NxK)
//   TRANS_B = false: C[m,n] = sum_k A[m,k] * B[k,n]   (B row-major KxN)
// Batched over grid.z; batch index z decomposes as z = zo*innerB + zi, and the
// per-matrix base offset is zo*s?o + zi*s?i (handles [B,H] head-sliced layouts).
// Tile: 64x64x16, 256 threads, 4x4 micro-tile per thread.
// Requires M,N % 64 == 0, K % 16 == 0 (true for all shapes here).
// ---------------------------------------------------------------------------
template <bool TRANS_B>
__global__ __launch_bounds__(256) void gemm64(
    const float* __restrict__ A, const float* __restrict__ Bm, float* __restrict__ C,
    int M, int N, int K, int lda, int ldb, int ldc,
    long long sAo, long long sAi, long long sBo, long long sBi,
    long long sCo, long long sCi, int innerB, float alpha)
{
    const int z = blockIdx.z;
    const int zo = z / innerB;
    const int zi = z - zo * innerB;
    A  += zo * sAo + zi * sAi;
    Bm += zo * sBo + zi * sBi;
    C  += zo * sCo + zi * sCi;

    __shared__ float As[16][65];
    __shared__ float Bs[16][TRANS_B ? 65 : 64];

    const int tid = threadIdx.x;
    const int tx = tid & 15;
    const int ty = tid >> 4;
    const int m0 = blockIdx.y * 64;
    const int n0 = blockIdx.x * 64;

    float acc[4][4] = {};

    const int arow = tid >> 2;           // 0..63
    const int acol = (tid & 3) << 2;     // 0,4,8,12

    for (int k0 = 0; k0 < K; k0 += 16) {
        // A tile: 64 rows x 16 k, transposed into As[k][m]
        {
            float4 a = *(const float4*)(A + (size_t)(m0 + arow) * lda + k0 + acol);
            As[acol + 0][arow] = a.x;
            As[acol + 1][arow] = a.y;
            As[acol + 2][arow] = a.z;
            As[acol + 3][arow] = a.w;
        }
        if (TRANS_B) {
            // B tile: 64 n-rows x 16 k, transposed into Bs[k][n]
            float4 b = *(const float4*)(Bm + (size_t)(n0 + arow) * ldb + k0 + acol);
            Bs[acol + 0][arow] = b.x;
            Bs[acol + 1][arow] = b.y;
            Bs[acol + 2][arow] = b.z;
            Bs[acol + 3][arow] = b.w;
        } else {
            // B tile: 16 k-rows x 64 n, stored directly Bs[k][n]
            const int brow = tid >> 4;          // 0..15
            const int bcol = (tid & 15) << 2;   // 0..60
            float4 b = *(const float4*)(Bm + (size_t)(k0 + brow) * ldb + n0 + bcol);
            Bs[brow][bcol + 0] = b.x;
            Bs[brow][bcol + 1] = b.y;
            Bs[brow][bcol + 2] = b.z;
            Bs[brow][bcol + 3] = b.w;
        }
        __syncthreads();

        #pragma unroll
        for (int kk = 0; kk < 16; kk++) {
            float af[4], bf[4];
            #pragma unroll
            for (int i = 0; i < 4; i++) af[i] = As[kk][ty * 4 + i];
            #pragma unroll
            for (int i = 0; i < 4; i++) bf[i] = Bs[kk][tx * 4 + i];
            #pragma unroll
            for (int i = 0; i < 4; i++)
                #pragma unroll
                for (int j = 0; j < 4; j++)
                    acc[i][j] = fmaf(af[i], bf[j], acc[i][j]);
        }
        __syncthreads();
    }

    #pragma unroll
    for (int i = 0; i < 4; i++) {
        #pragma unroll
        for (int j = 0; j < 4; j++) {
            C[(size_t)(m0 + ty * 4 + i) * ldc + n0 + tx * 4 + j] = alpha * acc[i][j];
        }
    }
}

// ---------------------------------------------------------------------------
// Row softmax over length SS=2048 rows; one block (256 thr) per row, in place.
// ---------------------------------------------------------------------------
__global__ __launch_bounds__(256) void softmax_kernel(float* __restrict__ attn)
{
    float* p = attn + (size_t)blockIdx.x * SS;
    const int t = threadIdx.x;

    float v[8];
    float m = -CUDART_INF_F;
    #pragma unroll
    for (int i = 0; i < 8; i++) {
        v[i] = p[t + i * 256];
        m = fmaxf(m, v[i]);
    }

    __shared__ float sred[8];
    #pragma unroll
    for (int o = 16; o; o >>= 1) m = fmaxf(m, __shfl_xor_sync(0xffffffffu, m, o));
    if ((t & 31) == 0) sred[t >> 5] = m;
    __syncthreads();
    m = sred[0];
    #pragma unroll
    for (int i = 1; i < 8; i++) m = fmaxf(m, sred[i]);

    float s = 0.f;
    #pragma unroll
    for (int i = 0; i < 8; i++) {
        v[i] = __expf(v[i] - m);
        s += v[i];
    }
    __syncthreads();
    #pragma unroll
    for (int o = 16; o; o >>= 1) s += __shfl_xor_sync(0xffffffffu, s, o);
    if ((t & 31) == 0) sred[t >> 5] = s;
    __syncthreads();
    s = sred[0];
    #pragma unroll
    for (int i = 1; i < 8; i++) s += sred[i];

    const float inv = 1.0f / s;
    #pragma unroll
    for (int i = 0; i < 8; i++) p[t + i * 256] = v[i] * inv;
}

// ---------------------------------------------------------------------------
// Fused: t = po + bo + x  (bias + residual), then LayerNorm(t)*gamma + beta
// One block per row of D=1024; 256 threads, 4 elements each.
// ---------------------------------------------------------------------------
__global__ __launch_bounds__(256) void ln_kernel(
    const float* __restrict__ po, const float* __restrict__ x,
    const float* __restrict__ bo, const float* __restrict__ gamma,
    const float* __restrict__ beta, float* __restrict__ y)
{
    const size_t row = blockIdx.x;
    const float* pr = po + row * DD;
    const float* xr = x + row * DD;
    float* yr = y + row * DD;
    const int t = threadIdx.x;

    float tv[4];
    float s = 0.f, s2 = 0.f;
    #pragma unroll
    for (int i = 0; i < 4; i++) {
        const int c = t + i * 256;
        const float u = pr[c] + bo[c] + xr[c];
        tv[i] = u;
        s += u;
        s2 += u * u;
    }

    __shared__ float r1[8], r2[8];
    #pragma unroll
    for (int o = 16; o; o >>= 1) {
        s  += __shfl_xor_sync(0xffffffffu, s, o);
        s2 += __shfl_xor_sync(0xffffffffu, s2, o);
    }
    if ((t & 31) == 0) { r1[t >> 5] = s; r2[t >> 5] = s2; }
    __syncthreads();
    s = r1[0]; s2 = r2[0];
    #pragma unroll
    for (int i = 1; i < 8; i++) { s += r1[i]; s2 += r2[i]; }

    const float mu = s * (1.0f / DD);
    const float var = s2 * (1.0f / DD) - mu * mu;
    const float inv = rsqrtf(var + 1e-5f);

    #pragma unroll
    for (int i = 0; i < 4; i++) {
        const int c = t + i * 256;
        yr[c] = (tv[i] - mu) * inv * gamma[c] + beta[c];
    }
}

// ---------------------------------------------------------------------------
extern "C" void kernel_launch(void* const* d_in, const int* in_sizes, int n_in,
                              void* d_out, int out_size)
{
    const float* x     = (const float*)d_in[0];
    const float* Wq    = (const float*)d_in[1];
    const float* Wk    = (const float*)d_in[2];
    const float* Wv    = (const float*)d_in[3];
    const float* Wo    = (const float*)d_in[4];
    const float* bo    = (const float*)d_in[5];
    const float* gamma = (const float*)d_in[6];
    const float* beta  = (const float*)d_in[7];

    float *q, *k, *v, *ctx, *po, *attn_scratch;
    cudaGetSymbolAddress((void**)&q,   g_q);
    cudaGetSymbolAddress((void**)&k,   g_k);
    cudaGetSymbolAddress((void**)&v,   g_v);
    cudaGetSymbolAddress((void**)&ctx, g_ctx);
    cudaGetSymbolAddress((void**)&po,  g_po);
    cudaGetSymbolAddress((void**)&attn_scratch, g_attn);

    const size_t Y   = (size_t)BB * SS * DD;               // 4,194,304
    const size_t ATT = (size_t)BB * HH * SS * SS;          // 134,217,728

    float* yout = (float*)d_out;
    // Reference returns (y, attn). If the harness expects both (flattened in
    // tuple order), write attn directly into d_out after y; otherwise scratch.
    float* attn = ((size_t)out_size >= Y + ATT) ? (yout + Y) : attn_scratch;

    const dim3 blk(256);
    const long long SD = (long long)SS * DD;     // per-batch stride of [B,S,D]
    const long long HSS = (long long)HH * SS * SS;
    const long long SSS = (long long)SS * SS;

    // Q/K/V projections: [4096,1024] = x @ W^T
    const dim3 gproj(DD / 64, (BB * SS) / 64, 1);
    gemm64<true><<<gproj, blk>>>(x, Wq, q, BB * SS, DD, DD, DD, DD, DD,
                                 0, 0, 0, 0, 0, 0, 1, 1.0f);
    gemm64<true><<<gproj, blk>>>(x, Wk, k, BB * SS, DD, DD, DD, DD, DD,
                                 0, 0, 0, 0, 0, 0, 1, 1.0f);
    gemm64<true><<<gproj, blk>>>(x, Wv, v, BB * SS, DD, DD, DD, DD, DD,
                                 0, 0, 0, 0, 0, 0, 1, 1.0f);

    // scores[b,h] = (Q_head @ K_head^T) / sqrt(dk); batch over z = b*H + h
    const dim3 gsc(SS / 64, SS / 64, BB * HH);
    gemm64<true><<<gsc, blk>>>(q, k, attn, SS, SS, DK, DD, DD, SS,
                               SD, DK, SD, DK, HSS, SSS, HH, 0.125f);

    // softmax rows in place
    softmax_kernel<<<BB * HH * SS, blk>>>(attn);

    // ctx[b,h] = attn @ V_head   (NN GEMM, N=64)
    const dim3 gctx(1, SS / 64, BB * HH);
    gemm64<false><<<gctx, blk>>>(attn, v, ctx, SS, DK, SS, SS, DD, DD,
                                 HSS, SSS, SD, DK, SD, DK, HH, 1.0f);

    // output projection: po = ctx @ Wo^T
    gemm64<true><<<gproj, blk>>>(ctx, Wo, po, BB * SS, DD, DD, DD, DD, DD,
                                 0, 0, 0, 0, 0, 0, 1, 1.0f);

    // bias + residual + LayerNorm -> y
    ln_kernel<<<BB * SS, blk>>>(po, x, bo, gamma, beta, yout);
}

// round 2
// speedup vs baseline: 2.4569x; 2.4569x over previous
#include <cuda_runtime.h>
#include <math_constants.h>

#define BB 2
#define SS 2048
#define DD 1024
#define HH 16
#define DK 64

// Scratch (allocation-free: __device__ globals)
__device__ float g_q[(size_t)BB * SS * DD];
__device__ float g_k[(size_t)BB * SS * DD];
__device__ float g_v[(size_t)BB * SS * DD];
__device__ float g_ctx[(size_t)BB * SS * DD];
__device__ float g_po[(size_t)BB * SS * DD];
__device__ float g_attn[(size_t)BB * HH * SS * SS];

__device__ __forceinline__ unsigned f2tf32(float x) {
    unsigned y;
    asm("cvt.rna.tf32.f32 %0, %1;" : "=r"(y) : "f"(x));
    return y;
}

__device__ __forceinline__ void mma_tf32(float* c, const unsigned* a, const unsigned* b) {
    asm volatile(
        "mma.sync.aligned.m16n8k8.row.col.f32.tf32.tf32.f32 "
        "{%0,%1,%2,%3}, {%4,%5,%6,%7}, {%8,%9}, {%0,%1,%2,%3};\n"
        : "+f"(c[0]), "+f"(c[1]), "+f"(c[2]), "+f"(c[3])
        : "r"(a[0]), "r"(a[1]), "r"(a[2]), "r"(a[3]), "r"(b[0]), "r"(b[1]));
}

// ---------------------------------------------------------------------------
// Tensor-core GEMM: C = alpha * A @ op(B), tf32 inputs / fp32 accumulate.
//   TRANS_B = true : C[m,n] = sum_k A[m,k] * B[n,k]
//   TRANS_B = false: C[m,n] = sum_k A[m,k] * B[k,n]
// Block tile BM x BN x 32, 256 threads (8 warps, 4x2), warp tile (BM/4)x(BN/2).
// Requires M%BM==0, N%BN==0, K%32==0 (true for all shapes here).
// Batched over grid.z with z = zo*innerB + zi offset decomposition.
// ---------------------------------------------------------------------------
template <int BM, int BN, bool TRANS_B>
__global__ __launch_bounds__(256) void gemm_tc(
    const float* __restrict__ A, const float* __restrict__ Bm, float* __restrict__ C,
    int M, int N, int K, int lda, int ldb, int ldc,
    long long sAo, long long sAi, long long sBo, long long sBi,
    long long sCo, long long sCi, int innerB, float alpha)
{
    constexpr int BK  = 32;
    constexpr int BKP = BK + 4;   // A smem row stride (conflict-free frag reads)
    constexpr int BNP = BN + 8;   // B smem row stride (conflict-free frag reads)
    constexpr int WM  = BM / 4;   // 32
    constexpr int WN  = BN / 2;   // 64 or 32
    constexpr int MT  = WM / 16;  // 2
    constexpr int NT  = WN / 8;   // 8 or 4

    __shared__ float As[BM][BKP];
    __shared__ float Bs[BK][BNP];

    const int z  = blockIdx.z;
    const int zo = z / innerB;
    const int zi = z - zo * innerB;
    A  += zo * sAo + zi * sAi;
    Bm += zo * sBo + zi * sBi;
    C  += zo * sCo + zi * sCi;

    const int tid  = threadIdx.x;
    const int warp = tid >> 5, lane = tid & 31;
    const int gid  = lane >> 2, tig = lane & 3;
    const int wm   = warp >> 1, wn = warp & 1;
    const int m0   = blockIdx.y * BM;
    const int n0   = blockIdx.x * BN;

    float acc[MT][NT][4] = {};

    const int arow = tid >> 3;        // 0..31
    const int acol = (tid & 7) * 4;   // 0..28

    for (int k0 = 0; k0 < K; k0 += BK) {
        // --- A tile: BM x 32, row-major in smem ---
        #pragma unroll
        for (int p = 0; p < BM / 32; p++) {
            const float4 a4 = *(const float4*)(A + (size_t)(m0 + p * 32 + arow) * lda + k0 + acol);
            *(float4*)&As[p * 32 + arow][acol] = a4;
        }
        // --- B tile -> Bs[k][n] ---
        if (TRANS_B) {
            #pragma unroll
            for (int p = 0; p < BN / 32; p++) {
                const int n = p * 32 + arow;
                const float4 b4 = *(const float4*)(Bm + (size_t)(n0 + n) * ldb + k0 + acol);
                Bs[acol + 0][n] = b4.x;
                Bs[acol + 1][n] = b4.y;
                Bs[acol + 2][n] = b4.z;
                Bs[acol + 3][n] = b4.w;
            }
        } else {
            constexpr int CPR = BN / 4;        // float4 slots per row
            constexpr int RPP = 256 / CPR;     // rows covered per pass
            const int brow = tid / CPR;
            const int bcol = (tid % CPR) * 4;
            #pragma unroll
            for (int p = 0; p < BK / RPP; p++) {
                const float4 b4 = *(const float4*)(Bm + (size_t)(k0 + p * RPP + brow) * ldb + n0 + bcol);
                *(float4*)&Bs[p * RPP + brow][bcol] = b4;
            }
        }
        __syncthreads();

        #pragma unroll
        for (int kk = 0; kk < BK; kk += 8) {
            unsigned af[MT][4], bf[NT][2];
            #pragma unroll
            for (int mt = 0; mt < MT; mt++) {
                const int mb = wm * WM + mt * 16;
                af[mt][0] = f2tf32(As[mb + gid    ][kk + tig    ]);
                af[mt][1] = f2tf32(As[mb + gid + 8][kk + tig    ]);
                af[mt][2] = f2tf32(As[mb + gid    ][kk + tig + 4]);
                af[mt][3] = f2tf32(As[mb + gid + 8][kk + tig + 4]);
            }
            #pragma unroll
            for (int nt = 0; nt < NT; nt++) {
                const int nb = wn * WN + nt * 8;
                bf[nt][0] = f2tf32(Bs[kk + tig    ][nb + gid]);
                bf[nt][1] = f2tf32(Bs[kk + tig + 4][nb + gid]);
            }
            #pragma unroll
            for (int mt = 0; mt < MT; mt++)
                #pragma unroll
                for (int nt = 0; nt < NT; nt++)
                    mma_tf32(acc[mt][nt], af[mt], bf[nt]);
        }
        __syncthreads();
    }

    #pragma unroll
    for (int mt = 0; mt < MT; mt++) {
        #pragma unroll
        for (int nt = 0; nt < NT; nt++) {
            const int r0 = m0 + wm * WM + mt * 16 + gid;
            const int c0 = n0 + wn * WN + nt * 8 + tig * 2;
            float2 v0 = { alpha * acc[mt][nt][0], alpha * acc[mt][nt][1] };
            float2 v1 = { alpha * acc[mt][nt][2], alpha * acc[mt][nt][3] };
            *(float2*)(C + (size_t)r0 * ldc + c0)       = v0;
            *(float2*)(C + (size_t)(r0 + 8) * ldc + c0) = v1;
        }
    }
}

// ---------------------------------------------------------------------------
// Row softmax over SS=2048 rows; one block (256 thr) per row, in place.
// ---------------------------------------------------------------------------
__global__ __launch_bounds__(256) void softmax_kernel(float* __restrict__ attn)
{
    float* p = attn + (size_t)blockIdx.x * SS;
    const int t = threadIdx.x;

    float v[8];
    float m = -CUDART_INF_F;
    #pragma unroll
    for (int i = 0; i < 8; i++) {
        v[i] = p[t + i * 256];
        m = fmaxf(m, v[i]);
    }

    __shared__ float sred[8];
    #pragma unroll
    for (int o = 16; o; o >>= 1) m = fmaxf(m, __shfl_xor_sync(0xffffffffu, m, o));
    if ((t & 31) == 0) sred[t >> 5] = m;
    __syncthreads();
    m = sred[0];
    #pragma unroll
    for (int i = 1; i < 8; i++) m = fmaxf(m, sred[i]);

    float s = 0.f;
    #pragma unroll
    for (int i = 0; i < 8; i++) {
        v[i] = __expf(v[i] - m);
        s += v[i];
    }
    __syncthreads();
    #pragma unroll
    for (int o = 16; o; o >>= 1) s += __shfl_xor_sync(0xffffffffu, s, o);
    if ((t & 31) == 0) sred[t >> 5] = s;
    __syncthreads();
    s = sred[0];
    #pragma unroll
    for (int i = 1; i < 8; i++) s += sred[i];

    const float inv = 1.0f / s;
    #pragma unroll
    for (int i = 0; i < 8; i++) p[t + i * 256] = v[i] * inv;
}

// ---------------------------------------------------------------------------
// Fused bias + residual + LayerNorm.
// ---------------------------------------------------------------------------
__global__ __launch_bounds__(256) void ln_kernel(
    const float* __restrict__ po, const float* __restrict__ x,
    const float* __restrict__ bo, const float* __restrict__ gamma,
    const float* __restrict__ beta, float* __restrict__ y)
{
    const size_t row = blockIdx.x;
    const float* pr = po + row * DD;
    const float* xr = x + row * DD;
    float* yr = y + row * DD;
    const int t = threadIdx.x;

    float tv[4];
    float s = 0.f, s2 = 0.f;
    #pragma unroll
    for (int i = 0; i < 4; i++) {
        const int c = t + i * 256;
        const float u = pr[c] + bo[c] + xr[c];
        tv[i] = u;
        s += u;
        s2 += u * u;
    }

    __shared__ float r1[8], r2[8];
    #pragma unroll
    for (int o = 16; o; o >>= 1) {
        s  += __shfl_xor_sync(0xffffffffu, s, o);
        s2 += __shfl_xor_sync(0xffffffffu, s2, o);
    }
    if ((t & 31) == 0) { r1[t >> 5] = s; r2[t >> 5] = s2; }
    __syncthreads();
    s = r1[0]; s2 = r2[0];
    #pragma unroll
    for (int i = 1; i < 8; i++) { s += r1[i]; s2 += r2[i]; }

    const float mu = s * (1.0f / DD);
    const float var = s2 * (1.0f / DD) - mu * mu;
    const float inv = rsqrtf(var + 1e-5f);

    #pragma unroll
    for (int i = 0; i < 4; i++) {
        const int c = t + i * 256;
        yr[c] = (tv[i] - mu) * inv * gamma[c] + beta[c];
    }
}

// ---------------------------------------------------------------------------
extern "C" void kernel_launch(void* const* d_in, const int* in_sizes, int n_in,
                              void* d_out, int out_size)
{
    const float* x     = (const float*)d_in[0];
    const float* Wq    = (const float*)d_in[1];
    const float* Wk    = (const float*)d_in[2];
    const float* Wv    = (const float*)d_in[3];
    const float* Wo    = (const float*)d_in[4];
    const float* bo    = (const float*)d_in[5];
    const float* gamma = (const float*)d_in[6];
    const float* beta  = (const float*)d_in[7];

    float *q, *k, *v, *ctx, *po, *attn_scratch;
    cudaGetSymbolAddress((void**)&q,   g_q);
    cudaGetSymbolAddress((void**)&k,   g_k);
    cudaGetSymbolAddress((void**)&v,   g_v);
    cudaGetSymbolAddress((void**)&ctx, g_ctx);
    cudaGetSymbolAddress((void**)&po,  g_po);
    cudaGetSymbolAddress((void**)&attn_scratch, g_attn);

    const size_t Y   = (size_t)BB * SS * DD;
    const size_t ATT = (size_t)BB * HH * SS * SS;

    float* yout = (float*)d_out;
    float* attn = ((size_t)out_size >= Y + ATT) ? (yout + Y) : attn_scratch;

    const dim3 blk(256);
    const long long SD  = (long long)SS * DD;
    const long long HSS = (long long)HH * SS * SS;
    const long long SSS = (long long)SS * SS;

    // Q/K/V projections: [4096,1024] = x @ W^T
    const dim3 gproj(DD / 128, (BB * SS) / 128, 1);
    gemm_tc<128, 128, true><<<gproj, blk>>>(x, Wq, q, BB * SS, DD, DD, DD, DD, DD,
                                            0, 0, 0, 0, 0, 0, 1, 1.0f);
    gemm_tc<128, 128, true><<<gproj, blk>>>(x, Wk, k, BB * SS, DD, DD, DD, DD, DD,
                                            0, 0, 0, 0, 0, 0, 1, 1.0f);
    gemm_tc<128, 128, true><<<gproj, blk>>>(x, Wv, v, BB * SS, DD, DD, DD, DD, DD,
                                            0, 0, 0, 0, 0, 0, 1, 1.0f);

    // scores[b,h] = (Q_head @ K_head^T) / sqrt(dk)
    const dim3 gsc(SS / 128, SS / 128, BB * HH);
    gemm_tc<128, 128, true><<<gsc, blk>>>(q, k, attn, SS, SS, DK, DD, DD, SS,
                                          SD, DK, SD, DK, HSS, SSS, HH, 0.125f);

    // softmax rows in place
    softmax_kernel<<<BB * HH * SS, blk>>>(attn);

    // ctx[b,h] = attn @ V_head   (NN GEMM, N=64, K=2048)
    const dim3 gctx(1, SS / 128, BB * HH);
    gemm_tc<128, 64, false><<<gctx, blk>>>(attn, v, ctx, SS, DK, SS, SS, DD, DD,
                                           HSS, SSS, SD, DK, SD, DK, HH, 1.0f);

    // output projection: po = ctx @ Wo^T
    gemm_tc<128, 128, true><<<gproj, blk>>>(ctx, Wo, po, BB * SS, DD, DD, DD, DD, DD,
                                            0, 0, 0, 0, 0, 0, 1, 1.0f);

    // bias + residual + LayerNorm -> y
    ln_kernel<<<BB * SS, blk>>>(po, x, bo, gamma, beta, yout);
}